// round 16
// baseline (speedup 1.0000x reference)
#include <cuda_runtime.h>
#include <cuda_bf16.h>
#include <cuda_fp16.h>
#include <math.h>
#include <stdint.h>

#define B_   4096
#define IN_  1024
#define H_   1024
#define F_   128
#define T_   3
#define G_   4096      // 4*H
#define LN_EPS 1e-5f

// ---------------- scratch (no allocations allowed) ----------------
__device__ __align__(16) __half g_wch[2][(size_t)F_ * IN_];  // wc fp16
__device__ __align__(16) __half g_a2h[2][(size_t)B_ * F_];   // stage1 out (fp16)
__device__ __align__(16) __half g_w2h[2][(size_t)G_ * F_];   // w_*_a  (fp16)
__device__ __align__(16) __half g_gates[2][(size_t)B_ * G_]; // ig / hg (fp16)
__device__ __align__(16) float2 g_s2part[2][B_][4];          // per-row LN partials

__device__ __forceinline__ uint32_t smem_u32(const void* p) {
    uint32_t a;
    asm("{ .reg .u64 t; cvta.to.shared.u64 t, %1; cvt.u32.u64 %0, t; }"
        : "=r"(a) : "l"(p));
    return a;
}
__device__ __forceinline__ void cp16(uint32_t dst, const void* src) {
    asm volatile("cp.async.cg.shared.global [%0], [%1], 16;"
                 :: "r"(dst), "l"(src));
}
#define CP_COMMIT()  asm volatile("cp.async.commit_group;")
#define CP_WAIT(n)   asm volatile("cp.async.wait_group %0;" :: "n"(n))

__device__ __forceinline__ float f4c(const float4& v, int c) {
    return reinterpret_cast<const float*>(&v)[c];
}
__device__ __forceinline__ float fexp2(float x) {
    float y; asm("ex2.approx.f32 %0, %1;" : "=f"(y) : "f"(x)); return y;
}
__device__ __forceinline__ float frcp(float x) {
    float y; asm("rcp.approx.f32 %0, %1;" : "=f"(y) : "f"(x)); return y;
}
__device__ __forceinline__ float sigm(float x) {
    return frcp(1.f + fexp2(-1.4426950408889634f * x));
}
__device__ __forceinline__ float tanh_fast(float x) {
    return 2.f * frcp(1.f + fexp2(-2.8853900817779268f * x)) - 1.f;
}

// =====================================================================
// convert_all: flat fp32 -> fp16 for wc + wa (x/hx folded into s1).
// =====================================================================
#define CV_WC  (F_ * IN_ / 4)
#define CV_WA  (G_ * F_ / 4)
#define CV_TOT (2 * CV_WC + 2 * CV_WA) // 327680 = 1280*256

__global__ __launch_bounds__(256) void convert_all_kernel(
    const float* __restrict__ wci, const float* __restrict__ wch,
    const float* __restrict__ wai, const float* __restrict__ wah)
{
    int idx = blockIdx.x * 256 + threadIdx.x;
    const float* src;
    __half* dst;
    if (idx < 2 * CV_WC) {
        int p = idx >= CV_WC; int off = idx - p * CV_WC;
        src = (p ? wch : wci) + off * 4;  dst = g_wch[p] + off * 4;
    } else {
        idx -= 2 * CV_WC;
        int p = idx >= CV_WA; int off = idx - p * CV_WA;
        src = (p ? wah : wai) + off * 4;  dst = g_w2h[p] + off * 4;
    }
    float4 v = *reinterpret_cast<const float4*>(src);
    __half2* d = reinterpret_cast<__half2*>(dst);
    d[0] = __floats2half2_rn(v.x, v.y);
    d[1] = __floats2half2_rn(v.z, v.w);
}

// =====================================================================
// Stage 1 (mma, fp16): C[b,f] = (x @ wc^T)[b,f] * scale(b,f).
// A read fp32 from gmem, converted on smem store; W via cp.async 2-buf.
// Tile M=64 x N=128, K=1024 chunks of 128 (x8). grid (64,2), 256 thr.
// =====================================================================
#define S1_LD   136
#define S1_ABUF (64 * S1_LD)
#define S1_WBUF (128 * S1_LD)
#define S1_TOT  ((S1_ABUF + 2 * S1_WBUF) * 2)   // 87040

__device__ __forceinline__ void s1_lda(
    float4* areg, const float* __restrict__ Xf, int row0, int j, int tid)
{
    int r = tid >> 2, q = tid & 3;
    const float4* src = reinterpret_cast<const float4*>(
        Xf + (size_t)(row0 + r) * IN_ + j * 128 + q * 32);
    #pragma unroll
    for (int i = 0; i < 8; i++) areg[i] = src[i];
}

__device__ __forceinline__ void s1_sta(
    const float4* areg, __half* As, int tid)
{
    int r = tid >> 2, q = tid & 3;
    __half2 tmp[16];
    #pragma unroll
    for (int i = 0; i < 8; i++) {
        tmp[2*i]   = __floats2half2_rn(areg[i].x, areg[i].y);
        tmp[2*i+1] = __floats2half2_rn(areg[i].z, areg[i].w);
    }
    uint4* dst = reinterpret_cast<uint4*>(As + r * S1_LD + q * 32);
    const uint4* s = reinterpret_cast<const uint4*>(tmp);
    #pragma unroll
    for (int i = 0; i < 4; i++) dst[i] = s[i];
}

__device__ __forceinline__ void s1_load_w(
    int j, uint32_t wBase, const __half* __restrict__ W, int tid)
{
    #pragma unroll
    for (int it = 0; it < 8; it++) {
        int idx = tid + it * 256;
        int r = idx >> 4, c = idx & 15;
        cp16(wBase + (uint32_t)(r * S1_LD + c * 8) * 2,
             W + (size_t)r * IN_ + j * 128 + c * 8);
    }
}

__global__ __launch_bounds__(256) void stage1_mma_kernel(
    const float* __restrict__ x_i, const float* __restrict__ x_h,
    const float* __restrict__ topic,
    const float* __restrict__ thw_i, const float* __restrict__ thb_i,
    const float* __restrict__ wb_i,
    const float* __restrict__ thw_h, const float* __restrict__ thb_h,
    const float* __restrict__ wb_h)
{
    extern __shared__ __half sm1[];
    __shared__ float sTheta[64][4];

    const int tid  = threadIdx.x;
    const int lane = tid & 31;
    const int wid  = tid >> 5;
    const int path = blockIdx.y;
    const int row0 = blockIdx.x * 64;

    const float* __restrict__ Xf = path ? x_h : x_i;
    const __half* __restrict__ W = g_wch[path];
    const float* __restrict__ thw = path ? thw_h : thw_i;
    const float* __restrict__ thb = path ? thb_h : thb_i;
    const float* __restrict__ wb  = path ? wb_h  : wb_i;
    __half* __restrict__ outp = g_a2h[path];

    if (tid < 192) {
        int r = tid / 3, t = tid - r * 3;
        const float* tp = topic + (size_t)(row0 + r) * T_;
        sTheta[r][t] = thb[t] + tp[0]*thw[t*T_+0] + tp[1]*thw[t*T_+1] + tp[2]*thw[t*T_+2];
    }

    __half* Asm = sm1;
    const uint32_t as_base = smem_u32(sm1);
    uint32_t wB[2] = { smem_u32(sm1 + S1_ABUF),
                       smem_u32(sm1 + S1_ABUF + S1_WBUF) };

    float4 areg[8];
    s1_lda(areg, Xf, row0, 0, tid);
    s1_load_w(0, wB[0], W, tid);
    CP_COMMIT();

    const int wm = (wid & 1) * 32;
    const int wn = (wid >> 1) * 32;
    const int lr  = lane & 7;
    const int seg = lane >> 3;
    const int l16 = lane & 15;

    float acc[2][4][4];
    #pragma unroll
    for (int mt = 0; mt < 2; mt++)
        #pragma unroll
        for (int nt = 0; nt < 4; nt++)
            #pragma unroll
            for (int j = 0; j < 4; j++) acc[mt][nt][j] = 0.f;

    for (int j = 0; j < 8; j++) {
        const int bf = j & 1;
        s1_sta(areg, Asm, tid);
        if (j < 7) {
            s1_lda(areg, Xf, row0, j + 1, tid);
            s1_load_w(j + 1, wB[(j+1)&1], W, tid);
            CP_COMMIT();
            CP_WAIT(1);
        } else {
            CP_WAIT(0);
        }
        __syncthreads();

        #pragma unroll
        for (int s = 0; s < 8; s++) {
            const int acol = s * 16 + ((seg >> 1) << 3);
            const int bcol = s * 16 + ((l16 >> 3) << 3);

            uint32_t a[2][4];
            #pragma unroll
            for (int mt = 0; mt < 2; mt++) {
                int arow = wm + mt * 16 + lr + ((seg & 1) << 3);
                uint32_t addr = as_base + (uint32_t)(arow * S1_LD + acol) * 2;
                asm volatile("ldmatrix.sync.aligned.m8n8.x4.shared.b16 {%0,%1,%2,%3}, [%4];"
                             : "=r"(a[mt][0]), "=r"(a[mt][1]),
                               "=r"(a[mt][2]), "=r"(a[mt][3])
                             : "r"(addr));
            }
            uint32_t b[4][2];
            #pragma unroll
            for (int nt = 0; nt < 4; nt++) {
                int brow = wn + nt * 8 + (l16 & 7);
                uint32_t addr = wB[bf] + (uint32_t)(brow * S1_LD + bcol) * 2;
                asm volatile("ldmatrix.sync.aligned.m8n8.x2.shared.b16 {%0,%1}, [%2];"
                             : "=r"(b[nt][0]), "=r"(b[nt][1])
                             : "r"(addr));
            }
            #pragma unroll
            for (int mt = 0; mt < 2; mt++)
                #pragma unroll
                for (int nt = 0; nt < 4; nt++) {
                    asm volatile(
                        "mma.sync.aligned.m16n8k16.row.col.f32.f16.f16.f32 "
                        "{%0,%1,%2,%3}, {%4,%5,%6,%7}, {%8,%9}, {%0,%1,%2,%3};"
                        : "+f"(acc[mt][nt][0]), "+f"(acc[mt][nt][1]),
                          "+f"(acc[mt][nt][2]), "+f"(acc[mt][nt][3])
                        : "r"(a[mt][0]), "r"(a[mt][1]), "r"(a[mt][2]), "r"(a[mt][3]),
                          "r"(b[nt][0]), "r"(b[nt][1]));
                }
        }
        __syncthreads();
    }

    const int em = lane >> 2;
    const int en = (lane & 3) * 2;
    #pragma unroll
    for (int nt = 0; nt < 4; nt++) {
        const int n = wn + nt * 8 + en;
        float w0a = wb[n*T_+0],     w1a = wb[n*T_+1],     w2a = wb[n*T_+2];
        float w0b = wb[(n+1)*T_+0], w1b = wb[(n+1)*T_+1], w2b = wb[(n+1)*T_+2];
        #pragma unroll
        for (int mt = 0; mt < 2; mt++) {
            #pragma unroll
            for (int half = 0; half < 2; half++) {
                int m = wm + mt * 16 + em + half * 8;
                float th0 = sTheta[m][0], th1 = sTheta[m][1], th2 = sTheta[m][2];
                float sc0 = th0*w0a + th1*w1a + th2*w2a;
                float sc1 = th0*w0b + th1*w1b + th2*w2b;
                float v0 = acc[mt][nt][half*2 + 0] * sc0;
                float v1 = acc[mt][nt][half*2 + 1] * sc1;
                *reinterpret_cast<__half2*>(&outp[(size_t)(row0 + m) * F_ + n]) =
                    __floats2half2_rn(v0, v1);
            }
        }
    }
}

// =====================================================================
// Stage 2: fp16 mma GEMM, K=128. A-resident, W-streamed.
// CTA tile 128 x 256, warp tile 64x64 (8 warps 2(M) x 4(N)).
// NCT=4 col tiles; also emits per-row LN partial (sum,sumsq) over its
// 1024-col span into g_s2part[path][row][blockIdx.x] (deterministic).
// grid = (4, 32, 2), 256 thr. smem 174080 B.
// =====================================================================
#define S2_LD    136
#define S2_ATILE (128 * S2_LD)
#define S2_WTILE (256 * S2_LD)
#define S2_TOT   ((S2_ATILE + 2 * S2_WTILE) * 2)    // 174080
#define NCT      4

__device__ __forceinline__ void s2_load_w(
    const __half* __restrict__ W, int col0, uint32_t base, int tid)
{
    #pragma unroll
    for (int it = 0; it < 16; it++) {
        int idx = tid + it * 256;
        int r = idx >> 4, c = idx & 15;
        cp16(base + (uint32_t)(r * S2_LD + c * 8) * 2,
             W + (size_t)(col0 + r) * F_ + c * 8);
    }
}

__global__ __launch_bounds__(256, 1) void stage2_mma_kernel()
{
    extern __shared__ __half sm2[];

    const int tid  = threadIdx.x;
    const int lane = tid & 31;
    const int wid  = tid >> 5;
    const int path = blockIdx.z;
    const int row0 = blockIdx.y * 128;
    const int ct0  = blockIdx.x * NCT;

    const __half* __restrict__ A = g_a2h[path];
    const __half* __restrict__ W = g_w2h[path];
    __half* __restrict__ O = g_gates[path];

    const uint32_t as_base = smem_u32(sm2);
    uint32_t wBuf[2] = { smem_u32(sm2 + S2_ATILE),
                         smem_u32(sm2 + S2_ATILE + S2_WTILE) };

    #pragma unroll
    for (int it = 0; it < 8; it++) {
        int idx = tid + it * 256;
        int r = idx >> 4, c = idx & 15;
        cp16(as_base + (uint32_t)(r * S2_LD + c * 8) * 2,
             A + (size_t)(row0 + r) * F_ + c * 8);
    }
    s2_load_w(W, ct0 * 256, wBuf[0], tid);
    CP_COMMIT();

    const int wm = (wid & 1) * 64;
    const int wn = (wid >> 1) * 64;
    const int lr  = lane & 7;
    const int seg = lane >> 3;
    const int em = lane >> 2;
    const int en = (lane & 3) * 2;

    float rsum[8], rsq[8];                       // per (mt, half) row stats
    #pragma unroll
    for (int k = 0; k < 8; k++) { rsum[k] = 0.f; rsq[k] = 0.f; }

    for (int it = 0; it < NCT; it++) {
        const int buf = it & 1;
        if (it + 1 < NCT) {
            s2_load_w(W, (ct0 + it + 1) * 256, wBuf[(it + 1) & 1], tid);
            CP_COMMIT();
            CP_WAIT(1);
        } else {
            CP_WAIT(0);
        }
        __syncthreads();

        float acc[4][8][4];
        #pragma unroll
        for (int mt = 0; mt < 4; mt++)
            #pragma unroll
            for (int nt = 0; nt < 8; nt++)
                #pragma unroll
                for (int j = 0; j < 4; j++) acc[mt][nt][j] = 0.f;

        const uint32_t bs_base = wBuf[buf];
        #pragma unroll
        for (int s = 0; s < 8; s++) {
            const int acol = s * 16 + ((seg >> 1) << 3);

            uint32_t a[4][4];
            #pragma unroll
            for (int mt = 0; mt < 4; mt++) {
                int arow = wm + mt * 16 + lr + ((seg & 1) << 3);
                uint32_t addr = as_base + (uint32_t)(arow * S2_LD + acol) * 2;
                asm volatile("ldmatrix.sync.aligned.m8n8.x4.shared.b16 {%0,%1,%2,%3}, [%4];"
                             : "=r"(a[mt][0]), "=r"(a[mt][1]),
                               "=r"(a[mt][2]), "=r"(a[mt][3])
                             : "r"(addr));
            }
            uint32_t b[4][4];
            #pragma unroll
            for (int ntp = 0; ntp < 4; ntp++) {
                int brow = wn + ntp * 16 + ((seg >> 1) << 3) + lr;
                int bcol = s * 16 + ((seg & 1) << 3);
                uint32_t addr = bs_base + (uint32_t)(brow * S2_LD + bcol) * 2;
                asm volatile("ldmatrix.sync.aligned.m8n8.x4.shared.b16 {%0,%1,%2,%3}, [%4];"
                             : "=r"(b[ntp][0]), "=r"(b[ntp][1]),
                               "=r"(b[ntp][2]), "=r"(b[ntp][3])
                             : "r"(addr));
            }
            #pragma unroll
            for (int mt = 0; mt < 4; mt++)
                #pragma unroll
                for (int nt = 0; nt < 8; nt++) {
                    const uint32_t b0 = b[nt >> 1][(nt & 1) * 2 + 0];
                    const uint32_t b1 = b[nt >> 1][(nt & 1) * 2 + 1];
                    asm volatile(
                        "mma.sync.aligned.m16n8k16.row.col.f32.f16.f16.f32 "
                        "{%0,%1,%2,%3}, {%4,%5,%6,%7}, {%8,%9}, {%0,%1,%2,%3};"
                        : "+f"(acc[mt][nt][0]), "+f"(acc[mt][nt][1]),
                          "+f"(acc[mt][nt][2]), "+f"(acc[mt][nt][3])
                        : "r"(a[mt][0]), "r"(a[mt][1]), "r"(a[mt][2]), "r"(a[mt][3]),
                          "r"(b0), "r"(b1));
                }
        }

        const int col0 = (ct0 + it) * 256;
        #pragma unroll
        for (int mt = 0; mt < 4; mt++) {
            #pragma unroll
            for (int nt = 0; nt < 8; nt++) {
                int m = row0 + wm + mt * 16 + em;
                int n = col0 + wn + nt * 8 + en;
                float v0 = acc[mt][nt][0], v1 = acc[mt][nt][1];
                float v2 = acc[mt][nt][2], v3 = acc[mt][nt][3];
                *reinterpret_cast<__half2*>(&O[(size_t)m * G_ + n]) =
                    __floats2half2_rn(v0, v1);
                *reinterpret_cast<__half2*>(&O[(size_t)(m + 8) * G_ + n]) =
                    __floats2half2_rn(v2, v3);
                rsum[mt*2+0] += v0 + v1;  rsq[mt*2+0] += v0*v0 + v1*v1;
                rsum[mt*2+1] += v2 + v3;  rsq[mt*2+1] += v2*v2 + v3*v3;
            }
        }
        __syncthreads();
    }

    // ---- combine row stats: en-group shfl, then N-warp combine in smem ----
    #pragma unroll
    for (int k = 0; k < 8; k++) {
        rsum[k] += __shfl_xor_sync(0xffffffffu, rsum[k], 1);
        rsum[k] += __shfl_xor_sync(0xffffffffu, rsum[k], 2);
        rsq[k]  += __shfl_xor_sync(0xffffffffu, rsq[k], 1);
        rsq[k]  += __shfl_xor_sync(0xffffffffu, rsq[k], 2);
    }
    float* sred = reinterpret_cast<float*>(sm2);   // reuse A region (done)
    if ((lane & 3) == 0) {
        #pragma unroll
        for (int mt = 0; mt < 4; mt++)
            #pragma unroll
            for (int half = 0; half < 2; half++) {
                int lrr = wm + mt * 16 + em + half * 8;
                sred[((wid >> 1) * 128 + lrr) * 2 + 0] = rsum[mt*2+half];
                sred[((wid >> 1) * 128 + lrr) * 2 + 1] = rsq[mt*2+half];
            }
    }
    __syncthreads();
    if (tid < 128) {
        float s = 0.f, q = 0.f;
        #pragma unroll
        for (int nw = 0; nw < 4; nw++) {
            s += sred[(nw * 128 + tid) * 2 + 0];
            q += sred[(nw * 128 + tid) * 2 + 1];
        }
        g_s2part[path][row0 + tid][blockIdx.x] = make_float2(s, q);
    }
}

// =====================================================================
// Stage 3: stats precomputed by stage2 -> single elementwise pass.
// =====================================================================
__device__ __forceinline__ float2 block_reduce2(float s, float q, float* red)
{
    __syncthreads();
    #pragma unroll
    for (int o = 16; o > 0; o >>= 1) {
        s += __shfl_xor_sync(0xffffffffu, s, o);
        q += __shfl_xor_sync(0xffffffffu, q, o);
    }
    int w = threadIdx.x >> 5, l = threadIdx.x & 31;
    if (l == 0) { red[w] = s; red[8 + w] = q; }
    __syncthreads();
    if (w == 0) {
        s = (l < 8) ? red[l] : 0.f;
        q = (l < 8) ? red[8 + l] : 0.f;
        #pragma unroll
        for (int o = 4; o > 0; o >>= 1) {
            s += __shfl_xor_sync(0xffffffffu, s, o);
            q += __shfl_xor_sync(0xffffffffu, q, o);
        }
        if (l == 0) { red[0] = s; red[1] = q; }
    }
    __syncthreads();
    return make_float2(red[0], red[1]);
}

__device__ __forceinline__ float4 unpack4(const uint2& u)
{
    float2 f0 = __half22float2(*reinterpret_cast<const __half2*>(&u.x));
    float2 f1 = __half22float2(*reinterpret_cast<const __half2*>(&u.y));
    return make_float4(f0.x, f0.y, f1.x, f1.y);
}

__global__ __launch_bounds__(256, 3) void stage3_kernel(
    const float* __restrict__ cx,
    const float* __restrict__ lniw, const float* __restrict__ lnib,
    const float* __restrict__ lnhw, const float* __restrict__ lnhb,
    const float* __restrict__ lncw, const float* __restrict__ lncb,
    float* __restrict__ out)
{
    __shared__ float red[16];

    const int r   = blockIdx.x;
    const int tid = threadIdx.x;
    const int j   = tid * 4;
    const __half* __restrict__ ig = g_gates[0] + (size_t)r * G_;
    const __half* __restrict__ hg = g_gates[1] + (size_t)r * G_;

    // LN stats from stage2 partials (uniform-address broadcast loads)
    const float4* P0 = reinterpret_cast<const float4*>(&g_s2part[0][r][0]);
    const float4* P1 = reinterpret_cast<const float4*>(&g_s2part[1][r][0]);
    float4 p0a = P0[0], p0b = P0[1], p1a = P1[0], p1b = P1[1];
    float si = p0a.x + p0a.z + p0b.x + p0b.z;
    float qi = p0a.y + p0a.w + p0b.y + p0b.w;
    float sh = p1a.x + p1a.z + p1b.x + p1b.z;
    float qh = p1a.y + p1a.w + p1b.y + p1b.w;
    float mu_i = si * (1.f / G_);
    float rstd_i = rsqrtf(qi * (1.f / G_) - mu_i * mu_i + LN_EPS);
    float mu_h = sh * (1.f / G_);
    float rstd_h = rsqrtf(qh * (1.f / G_) - mu_h * mu_h + LN_EPS);

    uint2 uig[4], uhg[4];
    #pragma unroll
    for (int g = 0; g < 4; g++) {
        uig[g] = *reinterpret_cast<const uint2*>(ig + g * H_ + j);
        uhg[g] = *reinterpret_cast<const uint2*>(hg + g * H_ + j);
    }
    float4 cxv = reinterpret_cast<const float4*>(cx + (size_t)r * H_)[tid];

    float4 gi_v[4], gh_v[4];
    #pragma unroll
    for (int g = 0; g < 4; g++) {
        gi_v[g] = unpack4(uig[g]);
        gh_v[g] = unpack4(uhg[g]);
    }

    const float4* lniw4 = reinterpret_cast<const float4*>(lniw);
    const float4* lnib4 = reinterpret_cast<const float4*>(lnib);
    const float4* lnhw4 = reinterpret_cast<const float4*>(lnhw);
    const float4* lnhb4 = reinterpret_cast<const float4*>(lnhb);

    float4 wi_v[4], bi_v[4], wh_v[4], bh_v[4];
    #pragma unroll
    for (int g = 0; g < 4; g++) {
        int n = g * 256 + tid;
        wi_v[g] = lniw4[n]; bi_v[g] = lnib4[n];
        wh_v[g] = lnhw4[n]; bh_v[g] = lnhb4[n];
    }

    float cc[4], oo[4];
    float cs = 0.f, cq = 0.f;
    #pragma unroll
    for (int c = 0; c < 4; c++) {
        #define GVAL(g) ((f4c(gi_v[g],c) - mu_i) * rstd_i * f4c(wi_v[g],c) + f4c(bi_v[g],c) + \
                         (f4c(gh_v[g],c) - mu_h) * rstd_h * f4c(wh_v[g],c) + f4c(bh_v[g],c))
        float gi = sigm(GVAL(0));
        float gf = sigm(GVAL(1));
        float gg = tanh_fast(GVAL(2));
        float go = sigm(GVAL(3));
        #undef GVAL
        float c_ = gf * f4c(cxv, c) + gi * gg;
        cc[c] = c_; oo[c] = go;
        cs += c_; cq += c_ * c_;
    }
    float2 rc = block_reduce2(cs, cq, red);
    float mu_c = rc.x * (1.f / H_);
    float rstd_c = rsqrtf(rc.y * (1.f / H_) - mu_c * mu_c + LN_EPS);

    float4 wcv = reinterpret_cast<const float4*>(lncw)[tid];
    float4 bcv = reinterpret_cast<const float4*>(lncb)[tid];
    float4 hyv, cyv;
    #pragma unroll
    for (int c = 0; c < 4; c++) {
        float cy = (cc[c] - mu_c) * rstd_c * f4c(wcv, c) + f4c(bcv, c);
        reinterpret_cast<float*>(&cyv)[c] = cy;
        reinterpret_cast<float*>(&hyv)[c] = oo[c] * tanh_fast(cy);
    }
    float4* out4 = reinterpret_cast<float4*>(out);
    out4[(size_t)r * 256 + tid] = hyv;
    out4[(size_t)B_ * 256 + (size_t)r * 256 + tid] = cyv;
}

// =====================================================================
extern "C" void kernel_launch(void* const* d_in, const int* in_sizes, int n_in,
                              void* d_out, int out_size)
{
    const float* input_ = (const float*)d_in[0];
    const float* hx     = (const float*)d_in[1];
    const float* cx     = (const float*)d_in[2];
    const float* topic  = (const float*)d_in[3];
    const float* w_ih_a = (const float*)d_in[4];
    const float* w_ih_b = (const float*)d_in[5];
    const float* w_ih_c = (const float*)d_in[6];
    const float* w_hh_a = (const float*)d_in[7];
    const float* w_hh_b = (const float*)d_in[8];
    const float* w_hh_c = (const float*)d_in[9];
    const float* th_ih_w = (const float*)d_in[10];
    const float* th_ih_b = (const float*)d_in[11];
    const float* th_hh_w = (const float*)d_in[12];
    const float* th_hh_b = (const float*)d_in[13];
    const float* ln_i_w  = (const float*)d_in[14];
    const float* ln_i_b  = (const float*)d_in[15];
    const float* ln_h_w  = (const float*)d_in[16];
    const float* ln_h_b  = (const float*)d_in[17];
    const float* ln_c_w  = (const float*)d_in[18];
    const float* ln_c_b  = (const float*)d_in[19];

    cudaFuncSetAttribute(stage1_mma_kernel,
                         cudaFuncAttributeMaxDynamicSharedMemorySize, S1_TOT);
    cudaFuncSetAttribute(stage2_mma_kernel,
                         cudaFuncAttributeMaxDynamicSharedMemorySize, S2_TOT);

    convert_all_kernel<<<CV_TOT / 256, 256>>>(w_ih_c, w_hh_c, w_ih_a, w_hh_a);

    stage1_mma_kernel<<<dim3(B_ / 64, 2), 256, S1_TOT>>>(
        input_, hx, topic, th_ih_w, th_ih_b, w_ih_b, th_hh_w, th_hh_b, w_hh_b);

    stage2_mma_kernel<<<dim3(G_ / 256 / NCT, B_ / 128, 2), 256, S2_TOT>>>();

    stage3_kernel<<<B_, 256>>>(cx, ln_i_w, ln_i_b, ln_h_w, ln_h_b,
                               ln_c_w, ln_c_b, (float*)d_out);
}